// round 1
// baseline (speedup 1.0000x reference)
#include <cuda_runtime.h>
#include <cuda_bf16.h>
#include <math.h>

// Problem constants
#define BATCH 2
#define SEQ   4096
#define EMB   1024
#define HEADS 16
#define HDIM  64
#define MROWS (BATCH*SEQ)   // 8192

// ---------------- scratch (static device globals; no runtime allocation) ----
__device__ float g_Q[(size_t)BATCH*HEADS*SEQ*HDIM];   // (B,H,T,D)
__device__ float g_K[(size_t)BATCH*HEADS*SEQ*HDIM];
__device__ float g_V[(size_t)BATCH*HEADS*SEQ*HDIM];
__device__ float g_AO[(size_t)BATCH*SEQ*EMB];         // (B,T,E) attention output

// ---------------- SGEMM: C[m][n] = sum_k A[m][k]*W[n][k] (+bias) -----------
// A: M x K row-major.  W: N x K row-major (torch Linear weight).
// mode 0: scatter output to (B,H,T,D) layout  (for Q/K/V)
// mode 1: plain row-major M x N output, add bias
#define BM 128
#define BN 128
#define BKT 16
#define TM 8
#define TN 8

__global__ __launch_bounds__(256) void sgemm_nt(
    const float* __restrict__ A, const float* __restrict__ W,
    const float* __restrict__ bias, float* __restrict__ out,
    int M, int N, int K, int mode)
{
    __shared__ float As[BKT][BM];
    __shared__ float Bs[BKT][BN];

    const int tid  = threadIdx.x;
    const int row0 = blockIdx.y * BM;
    const int col0 = blockIdx.x * BN;

    const int trow = (tid / 16) * TM;   // 0..120
    const int tcol = (tid % 16) * TN;   // 0..120

    float acc[TM][TN];
    #pragma unroll
    for (int i = 0; i < TM; i++)
        #pragma unroll
        for (int j = 0; j < TN; j++) acc[i][j] = 0.f;

    for (int k0 = 0; k0 < K; k0 += BKT) {
        // load 128x16 tiles of A and W (512 float4 each side / 256 threads)
        #pragma unroll
        for (int l = 0; l < 2; l++) {
            int idx = tid + l * 256;        // 0..511
            int r   = idx >> 2;             // 0..127
            int c4  = (idx & 3) * 4;        // 0,4,8,12
            float4 a = *(const float4*)&A[(size_t)(row0 + r) * K + k0 + c4];
            As[c4+0][r] = a.x; As[c4+1][r] = a.y;
            As[c4+2][r] = a.z; As[c4+3][r] = a.w;
            float4 b = *(const float4*)&W[(size_t)(col0 + r) * K + k0 + c4];
            Bs[c4+0][r] = b.x; Bs[c4+1][r] = b.y;
            Bs[c4+2][r] = b.z; Bs[c4+3][r] = b.w;
        }
        __syncthreads();

        #pragma unroll
        for (int kk = 0; kk < BKT; kk++) {
            float ar[TM], br[TN];
            float4 a0 = *(const float4*)&As[kk][trow];
            float4 a1 = *(const float4*)&As[kk][trow + 4];
            ar[0]=a0.x; ar[1]=a0.y; ar[2]=a0.z; ar[3]=a0.w;
            ar[4]=a1.x; ar[5]=a1.y; ar[6]=a1.z; ar[7]=a1.w;
            float4 b0 = *(const float4*)&Bs[kk][tcol];
            float4 b1 = *(const float4*)&Bs[kk][tcol + 4];
            br[0]=b0.x; br[1]=b0.y; br[2]=b0.z; br[3]=b0.w;
            br[4]=b1.x; br[5]=b1.y; br[6]=b1.z; br[7]=b1.w;
            #pragma unroll
            for (int i = 0; i < TM; i++)
                #pragma unroll
                for (int j = 0; j < TN; j++)
                    acc[i][j] = fmaf(ar[i], br[j], acc[i][j]);
        }
        __syncthreads();
    }

    if (mode == 1) {
        #pragma unroll
        for (int i = 0; i < TM; i++) {
            int m = row0 + trow + i;
            #pragma unroll
            for (int j = 0; j < TN; j += 4) {
                int n = col0 + tcol + j;
                float4 v;
                v.x = acc[i][j+0] + bias[n+0];
                v.y = acc[i][j+1] + bias[n+1];
                v.z = acc[i][j+2] + bias[n+2];
                v.w = acc[i][j+3] + bias[n+3];
                *(float4*)&out[(size_t)m * N + n] = v;
            }
        }
    } else {
        // scatter: m = b*SEQ + t ; n = h*HDIM + d  ->  (((b*HEADS+h)*SEQ)+t)*HDIM + d
        #pragma unroll
        for (int i = 0; i < TM; i++) {
            int m = row0 + trow + i;
            int b = m >> 12;            // /SEQ (4096)
            int t = m & (SEQ - 1);
            #pragma unroll
            for (int j = 0; j < TN; j += 4) {
                int n = col0 + tcol + j;
                int h = n >> 6;         // /HDIM
                int d = n & (HDIM - 1);
                float4 v = make_float4(acc[i][j], acc[i][j+1], acc[i][j+2], acc[i][j+3]);
                *(float4*)&g_Q[0] ; // (placeholder avoided below)
                size_t o = (((size_t)b * HEADS + h) * SEQ + t) * HDIM + d;
                *(float4*)&out[o] = v;
            }
        }
    }
}

// ---------------- Flash attention (fp32, causal, online softmax) ------------
// grid: (SEQ/64, B*H), block: 256 threads (16x16 logical).
// smem: Qt[d][r], Kt[d][c], Vs[kk][d], Ss[r][kk], each 64 x 68 floats.
#define ATS 64
#define APAD 68

__global__ __launch_bounds__(256) void flash_attn(
    const float* __restrict__ Q, const float* __restrict__ K,
    const float* __restrict__ V, float* __restrict__ O)
{
    extern __shared__ float sm[];
    float* Qt = sm;                    // [64][68] : Qt[d*68 + r]
    float* Kt = Qt + ATS * APAD;       // [64][68] : Kt[d*68 + c]
    float* Vs = Kt + ATS * APAD;       // [64][68] : Vs[kk*68 + d]
    float* Ss = Vs + ATS * APAD;       // [64][68] : Ss[r*68 + kk]

    const int qt = blockIdx.x;
    const int bh = blockIdx.y;
    const size_t base = (size_t)bh * SEQ * HDIM;
    const float* Qb = Q + base;
    const float* Kb = K + base;
    const float* Vb = V + base;

    const int tid = threadIdx.x;
    const int tx  = tid & 15;
    const int ty  = tid >> 4;
    const int r0  = ty * 4;
    const int c0  = tx * 4;
    const int q0  = qt * ATS;

    // load Q tile transposed (d-major)
    #pragma unroll
    for (int l = 0; l < 4; l++) {
        int idx = tid + l * 256;       // 0..1023 float4 slots
        int r   = idx >> 4;            // 0..63
        int d4  = (idx & 15) * 4;
        float4 v = *(const float4*)&Qb[(size_t)(q0 + r) * HDIM + d4];
        Qt[(d4+0)*APAD + r] = v.x;
        Qt[(d4+1)*APAD + r] = v.y;
        Qt[(d4+2)*APAD + r] = v.z;
        Qt[(d4+3)*APAD + r] = v.w;
    }

    float mrow[4], lrow[4], o[4][4];
    #pragma unroll
    for (int i = 0; i < 4; i++) {
        mrow[i] = -INFINITY; lrow[i] = 0.f;
        #pragma unroll
        for (int j = 0; j < 4; j++) o[i][j] = 0.f;
    }

    const float scale = 0.125f; // 1/sqrt(64)
    const unsigned FULL = 0xffffffffu;

    for (int jt = 0; jt <= qt; jt++) {
        __syncthreads();   // Q visible (iter 0); protect Kt/Vs/Ss reuse
        // load K tile (transposed) and V tile (natural)
        #pragma unroll
        for (int l = 0; l < 4; l++) {
            int idx = tid + l * 256;
            int r   = idx >> 4;
            int d4  = (idx & 15) * 4;
            size_t g = (size_t)(jt * ATS + r) * HDIM + d4;
            float4 kv = *(const float4*)&Kb[g];
            Kt[(d4+0)*APAD + r] = kv.x;
            Kt[(d4+1)*APAD + r] = kv.y;
            Kt[(d4+2)*APAD + r] = kv.z;
            Kt[(d4+3)*APAD + r] = kv.w;
            float4 vv = *(const float4*)&Vb[g];
            *(float4*)&Vs[r * APAD + d4] = vv;
        }
        __syncthreads();

        // S = Q K^T  (4x4 per thread)
        float s[4][4];
        #pragma unroll
        for (int i = 0; i < 4; i++)
            #pragma unroll
            for (int j = 0; j < 4; j++) s[i][j] = 0.f;

        #pragma unroll 8
        for (int kk = 0; kk < ATS; kk++) {
            float4 a = *(const float4*)&Qt[kk * APAD + r0];
            float4 b = *(const float4*)&Kt[kk * APAD + c0];
            float ar[4] = {a.x, a.y, a.z, a.w};
            float br[4] = {b.x, b.y, b.z, b.w};
            #pragma unroll
            for (int i = 0; i < 4; i++)
                #pragma unroll
                for (int j = 0; j < 4; j++)
                    s[i][j] = fmaf(ar[i], br[j], s[i][j]);
        }

        const bool diag = (jt == qt);
        #pragma unroll
        for (int i = 0; i < 4; i++) {
            #pragma unroll
            for (int j = 0; j < 4; j++) {
                s[i][j] *= scale;
                if (diag && (jt * ATS + c0 + j > q0 + r0 + i))
                    s[i][j] = -INFINITY;
            }
        }

        // online softmax per row
        #pragma unroll
        for (int i = 0; i < 4; i++) {
            float tmax = fmaxf(fmaxf(s[i][0], s[i][1]), fmaxf(s[i][2], s[i][3]));
            #pragma unroll
            for (int off = 8; off > 0; off >>= 1)
                tmax = fmaxf(tmax, __shfl_xor_sync(FULL, tmax, off, 16));
            float mn = fmaxf(mrow[i], tmax);
            float f  = expf(mrow[i] - mn);   // 0 when mrow == -inf
            float rs = 0.f;
            #pragma unroll
            for (int j = 0; j < 4; j++) {
                float p = expf(s[i][j] - mn);
                Ss[(r0 + i) * APAD + c0 + j] = p;
                rs += p;
            }
            #pragma unroll
            for (int off = 8; off > 0; off >>= 1)
                rs += __shfl_xor_sync(FULL, rs, off, 16);
            lrow[i] = lrow[i] * f + rs;
            mrow[i] = mn;
            #pragma unroll
            for (int j = 0; j < 4; j++) o[i][j] *= f;
        }
        __syncthreads();  // Ss fully written

        // O += P @ V
        #pragma unroll 8
        for (int kk = 0; kk < ATS; kk++) {
            float a0 = Ss[(r0+0) * APAD + kk];
            float a1 = Ss[(r0+1) * APAD + kk];
            float a2 = Ss[(r0+2) * APAD + kk];
            float a3 = Ss[(r0+3) * APAD + kk];
            float4 b = *(const float4*)&Vs[kk * APAD + c0];
            float br[4] = {b.x, b.y, b.z, b.w};
            #pragma unroll
            for (int j = 0; j < 4; j++) {
                o[0][j] = fmaf(a0, br[j], o[0][j]);
                o[1][j] = fmaf(a1, br[j], o[1][j]);
                o[2][j] = fmaf(a2, br[j], o[2][j]);
                o[3][j] = fmaf(a3, br[j], o[3][j]);
            }
        }
    }

    // epilogue: write (B,T,H,D) so downstream GEMM sees (B,T,E) rows
    const int b = bh >> 4;       // /HEADS
    const int h = bh & (HEADS - 1);
    #pragma unroll
    for (int i = 0; i < 4; i++) {
        float inv = 1.f / lrow[i];
        float4 v = make_float4(o[i][0]*inv, o[i][1]*inv, o[i][2]*inv, o[i][3]*inv);
        size_t off = (((size_t)b * SEQ + (q0 + r0 + i)) * HEADS + h) * (size_t)HDIM + c0;
        *(float4*)&O[off] = v;
    }
}

// ---------------- launch -----------------------------------------------------
extern "C" void kernel_launch(void* const* d_in, const int* in_sizes, int n_in,
                              void* d_out, int out_size)
{
    const float* x  = (const float*)d_in[0];
    const float* Wq = (const float*)d_in[1];
    const float* Wk = (const float*)d_in[2];
    const float* Wv = (const float*)d_in[3];
    const float* Wo = (const float*)d_in[4];
    const float* bo = (const float*)d_in[5];
    float* out = (float*)d_out;

    float *Qp, *Kp, *Vp, *Ap;
    cudaGetSymbolAddress((void**)&Qp, g_Q);
    cudaGetSymbolAddress((void**)&Kp, g_K);
    cudaGetSymbolAddress((void**)&Vp, g_V);
    cudaGetSymbolAddress((void**)&Ap, g_AO);

    dim3 gg(EMB / BN, MROWS / BM);     // (8, 64)

    sgemm_nt<<<gg, 256>>>(x, Wq, nullptr, Qp, MROWS, EMB, EMB, 0);
    sgemm_nt<<<gg, 256>>>(x, Wk, nullptr, Kp, MROWS, EMB, EMB, 0);
    sgemm_nt<<<gg, 256>>>(x, Wv, nullptr, Vp, MROWS, EMB, EMB, 0);

    static const int smem = ATS * APAD * 4 * sizeof(float);  // 69632
    cudaFuncSetAttribute(flash_attn, cudaFuncAttributeMaxDynamicSharedMemorySize, smem);
    flash_attn<<<dim3(SEQ / ATS, BATCH * HEADS), 256, smem>>>(Qp, Kp, Vp, Ap);

    sgemm_nt<<<gg, 256>>>(Ap, Wo, bo, out, MROWS, EMB, EMB, 1);
}

// round 3
// speedup vs baseline: 1.4012x; 1.4012x over previous
#include <cuda_runtime.h>
#include <cuda_bf16.h>
#include <math.h>
#include <cstdint>

// Problem constants
#define BATCH 2
#define SEQ   4096
#define EMB   1024
#define HEADS 16
#define HDIM  64
#define MROWS (BATCH*SEQ)   // 8192

// ---------------- scratch (static device globals; no runtime allocation) ----
__device__ float g_Q[(size_t)BATCH*HEADS*SEQ*HDIM];   // (B,H,T,D)
__device__ float g_K[(size_t)BATCH*HEADS*SEQ*HDIM];
__device__ float g_V[(size_t)BATCH*HEADS*SEQ*HDIM];
__device__ float g_AO[(size_t)BATCH*SEQ*EMB];         // (B,T,E) attention output

__device__ __forceinline__ uint32_t f2tf32(float f) {
    uint32_t r;
    asm("cvt.rna.tf32.f32 %0, %1;" : "=r"(r) : "f"(f));
    return r;
}

__device__ __forceinline__ void mma_tf32(
    float& c0, float& c1, float& c2, float& c3,
    uint32_t a0, uint32_t a1, uint32_t a2, uint32_t a3,
    uint32_t b0, uint32_t b1)
{
    asm volatile(
        "mma.sync.aligned.m16n8k8.row.col.f32.tf32.tf32.f32 "
        "{%0,%1,%2,%3}, {%4,%5,%6,%7}, {%8,%9}, {%0,%1,%2,%3};"
        : "+f"(c0), "+f"(c1), "+f"(c2), "+f"(c3)
        : "r"(a0), "r"(a1), "r"(a2), "r"(a3), "r"(b0), "r"(b1));
}

// ============================================================================
// tf32 mma.sync GEMM:  C[m][n] = sum_k A[m][k] * W[n][k]  (+bias)
// A: M x K row-major fp32.  W: N x K row-major fp32 (torch Linear weight).
// CTA 128x128x32, 256 threads = 8 warps (2 x 4), warp tile 64x32.
// mode 0: scatter to (B,H,T,D);  mode 1: row-major MxN + bias.
// ============================================================================
#define GBM 128
#define GBN 128
#define GBK 32
#define GPAD 36   // row stride in floats (144 B) — conflict-free frag loads

__global__ __launch_bounds__(256) void gemm_mma(
    const float* __restrict__ A, const float* __restrict__ W,
    const float* __restrict__ bias, float* __restrict__ out,
    int M, int N, int K, int mode)
{
    __shared__ float As[GBM * GPAD];
    __shared__ float Bs[GBN * GPAD];

    const int tid = threadIdx.x;
    const int wid = tid >> 5;
    const int lid = tid & 31;
    const int qrow = lid >> 2;   // 0..7
    const int qcol = lid & 3;    // 0..3

    const int row0 = blockIdx.y * GBM;
    const int col0 = blockIdx.x * GBN;

    const int wm0 = (wid & 1) * 64;   // warp m offset in tile
    const int wn0 = (wid >> 1) * 32;  // warp n offset in tile

    float c[4][4][4];                 // [m-tile][n-tile][frag]
    #pragma unroll
    for (int i = 0; i < 4; i++)
        #pragma unroll
        for (int j = 0; j < 4; j++)
            #pragma unroll
            for (int f = 0; f < 4; f++) c[i][j][f] = 0.f;

    for (int k0 = 0; k0 < K; k0 += GBK) {
        // load 128x32 A and W tiles: 1024 float4 slots each / 256 threads
        #pragma unroll
        for (int l = 0; l < 4; l++) {
            int idx = tid + l * 256;         // 0..1023
            int r   = idx >> 3;              // 0..127
            int c4  = (idx & 7) * 4;         // 0..28
            float4 va = *(const float4*)&A[(size_t)(row0 + r) * K + k0 + c4];
            *(float4*)&As[r * GPAD + c4] = va;
            float4 vb = *(const float4*)&W[(size_t)(col0 + r) * K + k0 + c4];
            *(float4*)&Bs[r * GPAD + c4] = vb;
        }
        __syncthreads();

        #pragma unroll
        for (int kk = 0; kk < GBK / 8; kk++) {
            const int kb = kk * 8;
            uint32_t a[4][4], b[4][2];
            #pragma unroll
            for (int mi = 0; mi < 4; mi++) {
                const float* ap = &As[(wm0 + mi * 16 + qrow) * GPAD + kb + qcol];
                a[mi][0] = f2tf32(ap[0]);
                a[mi][1] = f2tf32(ap[8 * GPAD]);
                a[mi][2] = f2tf32(ap[4]);
                a[mi][3] = f2tf32(ap[8 * GPAD + 4]);
            }
            #pragma unroll
            for (int ni = 0; ni < 4; ni++) {
                const float* bp = &Bs[(wn0 + ni * 8 + qrow) * GPAD + kb + qcol];
                b[ni][0] = f2tf32(bp[0]);
                b[ni][1] = f2tf32(bp[4]);
            }
            #pragma unroll
            for (int mi = 0; mi < 4; mi++)
                #pragma unroll
                for (int ni = 0; ni < 4; ni++)
                    mma_tf32(c[mi][ni][0], c[mi][ni][1], c[mi][ni][2], c[mi][ni][3],
                             a[mi][0], a[mi][1], a[mi][2], a[mi][3],
                             b[ni][0], b[ni][1]);
        }
        __syncthreads();
    }

    // epilogue
    #pragma unroll
    for (int mi = 0; mi < 4; mi++) {
        #pragma unroll
        for (int half = 0; half < 2; half++) {
            const int m = row0 + wm0 + mi * 16 + qrow + half * 8;
            const int bi = m >> 12;            // /SEQ
            const int t  = m & (SEQ - 1);
            #pragma unroll
            for (int ni = 0; ni < 4; ni++) {
                const int n = col0 + wn0 + ni * 8 + qcol * 2;
                float v0 = c[mi][ni][half * 2 + 0];
                float v1 = c[mi][ni][half * 2 + 1];
                if (mode == 0) {
                    const int h = n >> 6;
                    const int d = n & (HDIM - 1);
                    float* dst = &out[(((size_t)bi * HEADS + h) * SEQ + t) * HDIM + d];
                    *(float2*)dst = make_float2(v0, v1);
                } else {
                    float2 bb = *(const float2*)&bias[n];
                    float* dst = &out[(size_t)m * N + n];
                    *(float2*)dst = make_float2(v0 + bb.x, v1 + bb.y);
                }
            }
        }
    }
}

// ---------------- Flash attention (fp32, causal, online softmax) ------------
#define ATS 64
#define APAD 68

__global__ __launch_bounds__(256) void flash_attn(
    const float* __restrict__ Q, const float* __restrict__ K,
    const float* __restrict__ V, float* __restrict__ O)
{
    extern __shared__ float sm[];
    float* Qt = sm;
    float* Kt = Qt + ATS * APAD;
    float* Vs = Kt + ATS * APAD;
    float* Ss = Vs + ATS * APAD;

    const int qt = blockIdx.x;
    const int bh = blockIdx.y;
    const size_t base = (size_t)bh * SEQ * HDIM;
    const float* Qb = Q + base;
    const float* Kb = K + base;
    const float* Vb = V + base;

    const int tid = threadIdx.x;
    const int tx  = tid & 15;
    const int ty  = tid >> 4;
    const int r0  = ty * 4;
    const int c0  = tx * 4;
    const int q0  = qt * ATS;

    #pragma unroll
    for (int l = 0; l < 4; l++) {
        int idx = tid + l * 256;
        int r   = idx >> 4;
        int d4  = (idx & 15) * 4;
        float4 v = *(const float4*)&Qb[(size_t)(q0 + r) * HDIM + d4];
        Qt[(d4+0)*APAD + r] = v.x;
        Qt[(d4+1)*APAD + r] = v.y;
        Qt[(d4+2)*APAD + r] = v.z;
        Qt[(d4+3)*APAD + r] = v.w;
    }

    float mrow[4], lrow[4], o[4][4];
    #pragma unroll
    for (int i = 0; i < 4; i++) {
        mrow[i] = -INFINITY; lrow[i] = 0.f;
        #pragma unroll
        for (int j = 0; j < 4; j++) o[i][j] = 0.f;
    }

    const float scale = 0.125f;
    const unsigned FULL = 0xffffffffu;

    for (int jt = 0; jt <= qt; jt++) {
        __syncthreads();
        #pragma unroll
        for (int l = 0; l < 4; l++) {
            int idx = tid + l * 256;
            int r   = idx >> 4;
            int d4  = (idx & 15) * 4;
            size_t g = (size_t)(jt * ATS + r) * HDIM + d4;
            float4 kv = *(const float4*)&Kb[g];
            Kt[(d4+0)*APAD + r] = kv.x;
            Kt[(d4+1)*APAD + r] = kv.y;
            Kt[(d4+2)*APAD + r] = kv.z;
            Kt[(d4+3)*APAD + r] = kv.w;
            float4 vv = *(const float4*)&Vb[g];
            *(float4*)&Vs[r * APAD + d4] = vv;
        }
        __syncthreads();

        float s[4][4];
        #pragma unroll
        for (int i = 0; i < 4; i++)
            #pragma unroll
            for (int j = 0; j < 4; j++) s[i][j] = 0.f;

        #pragma unroll 8
        for (int kk = 0; kk < ATS; kk++) {
            float4 a = *(const float4*)&Qt[kk * APAD + r0];
            float4 b = *(const float4*)&Kt[kk * APAD + c0];
            float ar[4] = {a.x, a.y, a.z, a.w};
            float br[4] = {b.x, b.y, b.z, b.w};
            #pragma unroll
            for (int i = 0; i < 4; i++)
                #pragma unroll
                for (int j = 0; j < 4; j++)
                    s[i][j] = fmaf(ar[i], br[j], s[i][j]);
        }

        const bool diag = (jt == qt);
        #pragma unroll
        for (int i = 0; i < 4; i++) {
            #pragma unroll
            for (int j = 0; j < 4; j++) {
                s[i][j] *= scale;
                if (diag && (jt * ATS + c0 + j > q0 + r0 + i))
                    s[i][j] = -INFINITY;
            }
        }

        #pragma unroll
        for (int i = 0; i < 4; i++) {
            float tmax = fmaxf(fmaxf(s[i][0], s[i][1]), fmaxf(s[i][2], s[i][3]));
            #pragma unroll
            for (int off = 8; off > 0; off >>= 1)
                tmax = fmaxf(tmax, __shfl_xor_sync(FULL, tmax, off, 16));
            float mn = fmaxf(mrow[i], tmax);
            float f  = __expf(mrow[i] - mn);
            float rs = 0.f;
            #pragma unroll
            for (int j = 0; j < 4; j++) {
                float p = __expf(s[i][j] - mn);
                Ss[(r0 + i) * APAD + c0 + j] = p;
                rs += p;
            }
            #pragma unroll
            for (int off = 8; off > 0; off >>= 1)
                rs += __shfl_xor_sync(FULL, rs, off, 16);
            lrow[i] = lrow[i] * f + rs;
            mrow[i] = mn;
            #pragma unroll
            for (int j = 0; j < 4; j++) o[i][j] *= f;
        }
        __syncthreads();

        #pragma unroll 8
        for (int kk = 0; kk < ATS; kk++) {
            float a0 = Ss[(r0+0) * APAD + kk];
            float a1 = Ss[(r0+1) * APAD + kk];
            float a2 = Ss[(r0+2) * APAD + kk];
            float a3 = Ss[(r0+3) * APAD + kk];
            float4 b = *(const float4*)&Vs[kk * APAD + c0];
            float br[4] = {b.x, b.y, b.z, b.w};
            #pragma unroll
            for (int j = 0; j < 4; j++) {
                o[0][j] = fmaf(a0, br[j], o[0][j]);
                o[1][j] = fmaf(a1, br[j], o[1][j]);
                o[2][j] = fmaf(a2, br[j], o[2][j]);
                o[3][j] = fmaf(a3, br[j], o[3][j]);
            }
        }
    }

    const int b = bh >> 4;
    const int h = bh & (HEADS - 1);
    #pragma unroll
    for (int i = 0; i < 4; i++) {
        float inv = 1.f / lrow[i];
        float4 v = make_float4(o[i][0]*inv, o[i][1]*inv, o[i][2]*inv, o[i][3]*inv);
        size_t off = (((size_t)b * SEQ + (q0 + r0 + i)) * HEADS + h) * (size_t)HDIM + c0;
        *(float4*)&O[off] = v;
    }
}

// ---------------- launch -----------------------------------------------------
extern "C" void kernel_launch(void* const* d_in, const int* in_sizes, int n_in,
                              void* d_out, int out_size)
{
    const float* x  = (const float*)d_in[0];
    const float* Wq = (const float*)d_in[1];
    const float* Wk = (const float*)d_in[2];
    const float* Wv = (const float*)d_in[3];
    const float* Wo = (const float*)d_in[4];
    const float* bo = (const float*)d_in[5];
    float* out = (float*)d_out;

    float *Qp, *Kp, *Vp, *Ap;
    cudaGetSymbolAddress((void**)&Qp, g_Q);
    cudaGetSymbolAddress((void**)&Kp, g_K);
    cudaGetSymbolAddress((void**)&Vp, g_V);
    cudaGetSymbolAddress((void**)&Ap, g_AO);

    dim3 gg(EMB / GBN, MROWS / GBM);   // (8, 64)
    gemm_mma<<<gg, 256>>>(x, Wq, nullptr, Qp, MROWS, EMB, EMB, 0);
    gemm_mma<<<gg, 256>>>(x, Wk, nullptr, Kp, MROWS, EMB, EMB, 0);
    gemm_mma<<<gg, 256>>>(x, Wv, nullptr, Vp, MROWS, EMB, EMB, 0);

    static const int smem = ATS * APAD * 4 * sizeof(float);  // 69632
    cudaFuncSetAttribute(flash_attn, cudaFuncAttributeMaxDynamicSharedMemorySize, smem);
    flash_attn<<<dim3(SEQ / ATS, BATCH * HEADS), 256, smem>>>(Qp, Kp, Vp, Ap);

    gemm_mma<<<gg, 256>>>(Ap, Wo, bo, out, MROWS, EMB, EMB, 1);
}

// round 4
// speedup vs baseline: 2.8010x; 1.9990x over previous
#include <cuda_runtime.h>
#include <cuda_bf16.h>
#include <math.h>
#include <cstdint>

// Problem constants
#define BATCH 2
#define SEQ   4096
#define EMB   1024
#define HEADS 16
#define HDIM  64
#define MROWS (BATCH*SEQ)   // 8192

// ---------------- scratch (static device globals; no runtime allocation) ----
__device__ float g_Q[(size_t)BATCH*HEADS*SEQ*HDIM];   // (B,H,T,D)
__device__ float g_K[(size_t)BATCH*HEADS*SEQ*HDIM];
__device__ float g_V[(size_t)BATCH*HEADS*SEQ*HDIM];
__device__ float g_AO[(size_t)BATCH*SEQ*EMB];         // (B,T,E) attention output

__device__ __forceinline__ uint32_t f2tf32(float f) {
    uint32_t r;
    asm("cvt.rna.tf32.f32 %0, %1;" : "=r"(r) : "f"(f));
    return r;
}

__device__ __forceinline__ void mma_tf32(
    float& c0, float& c1, float& c2, float& c3,
    uint32_t a0, uint32_t a1, uint32_t a2, uint32_t a3,
    uint32_t b0, uint32_t b1)
{
    asm volatile(
        "mma.sync.aligned.m16n8k8.row.col.f32.tf32.tf32.f32 "
        "{%0,%1,%2,%3}, {%4,%5,%6,%7}, {%8,%9}, {%0,%1,%2,%3};"
        : "+f"(c0), "+f"(c1), "+f"(c2), "+f"(c3)
        : "r"(a0), "r"(a1), "r"(a2), "r"(a3), "r"(b0), "r"(b1));
}

// ============================================================================
// tf32 mma.sync GEMM:  C[m][n] = sum_k A[m][k] * W[n][k]  (+bias)
// smem holds pre-converted tf32 (no cvt in inner loop).
// CTA 128x128x32, 256 threads = 8 warps (2x4), warp tile 64x32.
// ============================================================================
#define GBM 128
#define GBN 128
#define GBK 32
#define GPAD 36

__global__ __launch_bounds__(256) void gemm_mma(
    const float* __restrict__ A, const float* __restrict__ W,
    const float* __restrict__ bias, float* __restrict__ out,
    int M, int N, int K, int mode)
{
    __shared__ uint32_t As[GBM * GPAD];
    __shared__ uint32_t Bs[GBN * GPAD];

    const int tid = threadIdx.x;
    const int wid = tid >> 5;
    const int lid = tid & 31;
    const int qrow = lid >> 2;
    const int qcol = lid & 3;

    const int row0 = blockIdx.y * GBM;
    const int col0 = blockIdx.x * GBN;
    const int wm0 = (wid & 1) * 64;
    const int wn0 = (wid >> 1) * 32;

    float c[4][4][4];
    #pragma unroll
    for (int i = 0; i < 4; i++)
        #pragma unroll
        for (int j = 0; j < 4; j++)
            #pragma unroll
            for (int f = 0; f < 4; f++) c[i][j][f] = 0.f;

    for (int k0 = 0; k0 < K; k0 += GBK) {
        #pragma unroll
        for (int l = 0; l < 4; l++) {
            int idx = tid + l * 256;
            int r   = idx >> 3;
            int c4  = (idx & 7) * 4;
            float4 va = *(const float4*)&A[(size_t)(row0 + r) * K + k0 + c4];
            *(uint4*)&As[r * GPAD + c4] =
                make_uint4(f2tf32(va.x), f2tf32(va.y), f2tf32(va.z), f2tf32(va.w));
            float4 vb = *(const float4*)&W[(size_t)(col0 + r) * K + k0 + c4];
            *(uint4*)&Bs[r * GPAD + c4] =
                make_uint4(f2tf32(vb.x), f2tf32(vb.y), f2tf32(vb.z), f2tf32(vb.w));
        }
        __syncthreads();

        #pragma unroll
        for (int kk = 0; kk < GBK / 8; kk++) {
            const int kb = kk * 8;
            uint32_t a[4][4], b[4][2];
            #pragma unroll
            for (int mi = 0; mi < 4; mi++) {
                const uint32_t* ap = &As[(wm0 + mi * 16 + qrow) * GPAD + kb + qcol];
                a[mi][0] = ap[0];
                a[mi][1] = ap[8 * GPAD];
                a[mi][2] = ap[4];
                a[mi][3] = ap[8 * GPAD + 4];
            }
            #pragma unroll
            for (int ni = 0; ni < 4; ni++) {
                const uint32_t* bp = &Bs[(wn0 + ni * 8 + qrow) * GPAD + kb + qcol];
                b[ni][0] = bp[0];
                b[ni][1] = bp[4];
            }
            #pragma unroll
            for (int mi = 0; mi < 4; mi++)
                #pragma unroll
                for (int ni = 0; ni < 4; ni++)
                    mma_tf32(c[mi][ni][0], c[mi][ni][1], c[mi][ni][2], c[mi][ni][3],
                             a[mi][0], a[mi][1], a[mi][2], a[mi][3],
                             b[ni][0], b[ni][1]);
        }
        __syncthreads();
    }

    #pragma unroll
    for (int mi = 0; mi < 4; mi++) {
        #pragma unroll
        for (int half = 0; half < 2; half++) {
            const int m = row0 + wm0 + mi * 16 + qrow + half * 8;
            const int bi = m >> 12;
            const int t  = m & (SEQ - 1);
            #pragma unroll
            for (int ni = 0; ni < 4; ni++) {
                const int n = col0 + wn0 + ni * 8 + qcol * 2;
                float v0 = c[mi][ni][half * 2 + 0];
                float v1 = c[mi][ni][half * 2 + 1];
                if (mode == 0) {
                    const int h = n >> 6;
                    const int d = n & (HDIM - 1);
                    *(float2*)&out[(((size_t)bi * HEADS + h) * SEQ + t) * HDIM + d] =
                        make_float2(v0, v1);
                } else {
                    float2 bb = *(const float2*)&bias[n];
                    *(float2*)&out[(size_t)m * N + n] = make_float2(v0 + bb.x, v1 + bb.y);
                }
            }
        }
    }
}

// ============================================================================
// Flash attention on tf32 mma.sync. 4 warps, Br=Bc=64, D=64.
// Q fragments in registers (scale folded in). K: [key][d], V: transposed [d][key],
// P staged through smem as tf32. Stride-68 padding: conflict-free frag loads.
// ============================================================================
#define FPAD 68
#define FSM_BYTES (3 * 64 * FPAD * 4)   // Ks + Vt + Ps = 52224

__global__ __launch_bounds__(128) void flash_mma(
    const float* __restrict__ Q, const float* __restrict__ K,
    const float* __restrict__ V, float* __restrict__ O)
{
    extern __shared__ uint32_t smF[];
    uint32_t* Ks = smF;                  // [key][d]   (also Q staging)
    uint32_t* Vt = smF + 64 * FPAD;      // [d][key]
    uint32_t* Ps = smF + 2 * 64 * FPAD;  // [q][key]

    const int qt = blockIdx.x;
    const int bh = blockIdx.y;
    const size_t base = (size_t)bh * SEQ * HDIM;
    const float* Qb = Q + base;
    const float* Kb = K + base;
    const float* Vb = V + base;

    const int tid  = threadIdx.x;
    const int wid  = tid >> 5;
    const int lid  = tid & 31;
    const int qrow = lid >> 2;     // 0..7
    const int qcol = lid & 3;      // 0..3
    const int w16  = wid * 16;
    const int q0   = qt * 64;
    const unsigned FULL = 0xffffffffu;

    // ---- stage Q (scaled) into Ks buffer, pull A-fragments to registers ----
    #pragma unroll
    for (int l = 0; l < 8; l++) {
        int idx = tid + l * 128;       // 0..1023 float4 slots
        int r   = idx >> 4;
        int d4  = (idx & 15) * 4;
        float4 v = *(const float4*)&Qb[(size_t)(q0 + r) * HDIM + d4];
        *(uint4*)&Ks[r * FPAD + d4] = make_uint4(
            f2tf32(v.x * 0.125f), f2tf32(v.y * 0.125f),
            f2tf32(v.z * 0.125f), f2tf32(v.w * 0.125f));
    }
    __syncthreads();

    uint32_t aq[8][4];
    #pragma unroll
    for (int ks = 0; ks < 8; ks++) {
        const uint32_t* p = &Ks[(w16 + qrow) * FPAD + ks * 8 + qcol];
        aq[ks][0] = p[0];
        aq[ks][1] = p[8 * FPAD];
        aq[ks][2] = p[4];
        aq[ks][3] = p[8 * FPAD + 4];
    }
    __syncthreads();

    float o[8][4];
    #pragma unroll
    for (int nt = 0; nt < 8; nt++)
        #pragma unroll
        for (int f = 0; f < 4; f++) o[nt][f] = 0.f;
    float m_lo = -INFINITY, m_hi = -INFINITY, l_lo = 0.f, l_hi = 0.f;

    for (int jt = 0; jt <= qt; jt++) {
        __syncthreads();   // protect Ks/Vt (PV of prev iter) before overwrite
        // ---- load K [key][d] and V transposed [d][key] ----
        #pragma unroll
        for (int l = 0; l < 8; l++) {
            int idx = tid + l * 128;
            int r   = idx >> 4;
            int d4  = (idx & 15) * 4;
            size_t g = (size_t)(jt * 64 + r) * HDIM + d4;
            float4 kv = *(const float4*)&Kb[g];
            *(uint4*)&Ks[r * FPAD + d4] =
                make_uint4(f2tf32(kv.x), f2tf32(kv.y), f2tf32(kv.z), f2tf32(kv.w));
            float4 vv = *(const float4*)&Vb[g];
            Vt[(d4 + 0) * FPAD + r] = f2tf32(vv.x);
            Vt[(d4 + 1) * FPAD + r] = f2tf32(vv.y);
            Vt[(d4 + 2) * FPAD + r] = f2tf32(vv.z);
            Vt[(d4 + 3) * FPAD + r] = f2tf32(vv.w);
        }
        __syncthreads();

        // ---- S = Q K^T ----
        float c[8][4];
        #pragma unroll
        for (int nt = 0; nt < 8; nt++)
            #pragma unroll
            for (int f = 0; f < 4; f++) c[nt][f] = 0.f;

        #pragma unroll
        for (int ks = 0; ks < 8; ks++) {
            #pragma unroll
            for (int nt = 0; nt < 8; nt++) {
                const uint32_t* bp = &Ks[(nt * 8 + qrow) * FPAD + ks * 8 + qcol];
                mma_tf32(c[nt][0], c[nt][1], c[nt][2], c[nt][3],
                         aq[ks][0], aq[ks][1], aq[ks][2], aq[ks][3],
                         bp[0], bp[4]);
            }
        }

        // ---- causal mask (diagonal tile only) ----
        if (jt == qt) {
            #pragma unroll
            for (int nt = 0; nt < 8; nt++) {
                #pragma unroll
                for (int f = 0; f < 4; f++) {
                    int kloc = nt * 8 + 2 * qcol + (f & 1);
                    int qloc = w16 + qrow + ((f >> 1) * 8);
                    if (kloc > qloc) c[nt][f] = -INFINITY;
                }
            }
        }

        // ---- online softmax ----
        float tl = -INFINITY, th = -INFINITY;
        #pragma unroll
        for (int nt = 0; nt < 8; nt++) {
            tl = fmaxf(tl, fmaxf(c[nt][0], c[nt][1]));
            th = fmaxf(th, fmaxf(c[nt][2], c[nt][3]));
        }
        tl = fmaxf(tl, __shfl_xor_sync(FULL, tl, 1, 4));
        tl = fmaxf(tl, __shfl_xor_sync(FULL, tl, 2, 4));
        th = fmaxf(th, __shfl_xor_sync(FULL, th, 1, 4));
        th = fmaxf(th, __shfl_xor_sync(FULL, th, 2, 4));

        float mn_lo = fmaxf(m_lo, tl);
        float mn_hi = fmaxf(m_hi, th);
        float f_lo = __expf(m_lo - mn_lo);
        float f_hi = __expf(m_hi - mn_hi);

        float rs_lo = 0.f, rs_hi = 0.f;
        #pragma unroll
        for (int nt = 0; nt < 8; nt++) {
            float p0 = __expf(c[nt][0] - mn_lo);
            float p1 = __expf(c[nt][1] - mn_lo);
            float p2 = __expf(c[nt][2] - mn_hi);
            float p3 = __expf(c[nt][3] - mn_hi);
            rs_lo += p0 + p1;
            rs_hi += p2 + p3;
            int col = nt * 8 + 2 * qcol;
            *(uint2*)&Ps[(w16 + qrow) * FPAD + col]     = make_uint2(f2tf32(p0), f2tf32(p1));
            *(uint2*)&Ps[(w16 + qrow + 8) * FPAD + col] = make_uint2(f2tf32(p2), f2tf32(p3));
        }
        rs_lo += __shfl_xor_sync(FULL, rs_lo, 1, 4);
        rs_lo += __shfl_xor_sync(FULL, rs_lo, 2, 4);
        rs_hi += __shfl_xor_sync(FULL, rs_hi, 1, 4);
        rs_hi += __shfl_xor_sync(FULL, rs_hi, 2, 4);

        l_lo = l_lo * f_lo + rs_lo;
        l_hi = l_hi * f_hi + rs_hi;
        m_lo = mn_lo;
        m_hi = mn_hi;
        #pragma unroll
        for (int nt = 0; nt < 8; nt++) {
            o[nt][0] *= f_lo; o[nt][1] *= f_lo;
            o[nt][2] *= f_hi; o[nt][3] *= f_hi;
        }
        __syncthreads();   // Ps complete

        // ---- O += P V ----
        #pragma unroll
        for (int ks = 0; ks < 8; ks++) {
            const uint32_t* pp = &Ps[(w16 + qrow) * FPAD + ks * 8 + qcol];
            uint32_t a0 = pp[0];
            uint32_t a1 = pp[8 * FPAD];
            uint32_t a2 = pp[4];
            uint32_t a3 = pp[8 * FPAD + 4];
            #pragma unroll
            for (int nt = 0; nt < 8; nt++) {
                const uint32_t* bp = &Vt[(nt * 8 + qrow) * FPAD + ks * 8 + qcol];
                mma_tf32(o[nt][0], o[nt][1], o[nt][2], o[nt][3],
                         a0, a1, a2, a3, bp[0], bp[4]);
            }
        }
    }

    // ---- epilogue: write (B,T,H,D) ----
    const float inv_lo = 1.f / l_lo;
    const float inv_hi = 1.f / l_hi;
    const int b = bh >> 4;
    const int h = bh & (HEADS - 1);
    const int row_lo = q0 + w16 + qrow;
    const int row_hi = row_lo + 8;
    #pragma unroll
    for (int nt = 0; nt < 8; nt++) {
        const int d = nt * 8 + 2 * qcol;
        *(float2*)&O[(((size_t)b * SEQ + row_lo) * HEADS + h) * HDIM + d] =
            make_float2(o[nt][0] * inv_lo, o[nt][1] * inv_lo);
        *(float2*)&O[(((size_t)b * SEQ + row_hi) * HEADS + h) * HDIM + d] =
            make_float2(o[nt][2] * inv_hi, o[nt][3] * inv_hi);
    }
}

// ---------------- launch -----------------------------------------------------
extern "C" void kernel_launch(void* const* d_in, const int* in_sizes, int n_in,
                              void* d_out, int out_size)
{
    const float* x  = (const float*)d_in[0];
    const float* Wq = (const float*)d_in[1];
    const float* Wk = (const float*)d_in[2];
    const float* Wv = (const float*)d_in[3];
    const float* Wo = (const float*)d_in[4];
    const float* bo = (const float*)d_in[5];
    float* out = (float*)d_out;

    float *Qp, *Kp, *Vp, *Ap;
    cudaGetSymbolAddress((void**)&Qp, g_Q);
    cudaGetSymbolAddress((void**)&Kp, g_K);
    cudaGetSymbolAddress((void**)&Vp, g_V);
    cudaGetSymbolAddress((void**)&Ap, g_AO);

    dim3 gg(EMB / GBN, MROWS / GBM);   // (8, 64)
    gemm_mma<<<gg, 256>>>(x, Wq, nullptr, Qp, MROWS, EMB, EMB, 0);
    gemm_mma<<<gg, 256>>>(x, Wk, nullptr, Kp, MROWS, EMB, EMB, 0);
    gemm_mma<<<gg, 256>>>(x, Wv, nullptr, Vp, MROWS, EMB, EMB, 0);

    cudaFuncSetAttribute(flash_mma, cudaFuncAttributeMaxDynamicSharedMemorySize, FSM_BYTES);
    flash_mma<<<dim3(SEQ / 64, BATCH * HEADS), 128, FSM_BYTES>>>(Qp, Kp, Vp, Ap);

    gemm_mma<<<gg, 256>>>(Ap, Wo, bo, out, MROWS, EMB, EMB, 1);
}